// round 3
// baseline (speedup 1.0000x reference)
#include <cuda_runtime.h>

#define NN 50000
#define EE 800000
#define EHALF (EE / 2)

typedef unsigned long long u64;

// ---------------- scratch (device globals; no allocation allowed) ----------
__device__ float g_SQa[NN * 2];
__device__ float g_SKa[NN * 2];
__device__ float g_SQb[NN * 2];
__device__ float g_SKb[NN * 2];
__device__ float g_vpa[NN * 64];
__device__ float g_vpb[NN * 64];
__device__ float g_sa[NN * 2];
__device__ float g_sb[NN * 2];
__device__ float g_agga[NN * 64];
__device__ float g_aggb[NN * 64];

__device__ __forceinline__ float tanh_h(float x) {
    float y;
    asm("tanh.approx.f32 %0, %1;" : "=f"(y) : "f"(x));
    return y;
}

__device__ __forceinline__ void red_add_v4(float* p, float4 v) {
    asm volatile("red.global.add.v4.f32 [%0], {%1, %2, %3, %4};"
                 :: "l"(p), "f"(v.x), "f"(v.y), "f"(v.z), "f"(v.w) : "memory");
}

__device__ __forceinline__ u64 pack2(float a, float b) {
    u64 r;
    asm("mov.b64 %0, {%1, %2};" : "=l"(r) : "f"(a), "f"(b));
    return r;
}
__device__ __forceinline__ void unpack2(u64 v, float& a, float& b) {
    asm("mov.b64 {%0, %1}, %2;" : "=f"(a), "=f"(b) : "l"(v));
}
__device__ __forceinline__ void ffma2(u64& d, u64 a, u64 b) {
    asm("fma.rn.f32x2 %0, %1, %2, %3;" : "=l"(d) : "l"(a), "l"(b), "l"(d));
}
__device__ __forceinline__ u64 mul2(u64 a, u64 b) {
    u64 r;
    asm("mul.rn.f32x2 %0, %1, %2;" : "=l"(r) : "l"(a), "l"(b));
    return r;
}

// ---------------- projection: per node compute SQ, SK scalars + vp row -----
__global__ void __launch_bounds__(128) proj_kernel(
    const float* __restrict__ x_a,
    const float* __restrict__ Wq_a, const float* __restrict__ Wk_a,
    const float* __restrict__ Wv_a,
    const float* __restrict__ emb_a, const float* __restrict__ rel_a,
    float* __restrict__ SQ_a, float* __restrict__ SK_a, float* __restrict__ vp_a,
    const float* __restrict__ x_b,
    const float* __restrict__ Wq_b, const float* __restrict__ Wk_b,
    const float* __restrict__ Wv_b,
    const float* __restrict__ emb_b, const float* __restrict__ rel_b,
    float* __restrict__ SQ_b, float* __restrict__ SK_b, float* __restrict__ vp_b,
    const float* __restrict__ a_attn, int pb)
{
    int typ = (blockIdx.x >= pb);
    int blk = typ ? (blockIdx.x - pb) : blockIdx.x;
    const float* x   = typ ? x_b   : x_a;
    const float* Wq  = typ ? Wq_b  : Wq_a;
    const float* Wk  = typ ? Wk_b  : Wk_a;
    const float* Wv  = typ ? Wv_b  : Wv_a;
    const float* emb = typ ? emb_b : emb_a;
    const float* rel = typ ? rel_b : rel_a;
    float* SQ = typ ? SQ_b : SQ_a;
    float* SK = typ ? SK_b : SK_a;
    float* vp = typ ? vp_b : vp_a;

    __shared__ float sW[3 * 64 * 64];  // Wq | Wk | Wv, 48KB
    int tid = threadIdx.x;
    for (int i = tid; i < 4096; i += 128) {
        sW[i]        = Wq[i];
        sW[4096 + i] = Wk[i];
        sW[8192 + i] = Wv[i];
    }
    __syncthreads();

    int node = blk * 128 + tid;
    if (node >= NN) return;

    float4 xr[16];
    const float4* xp = reinterpret_cast<const float4*>(x + node * 64);
#pragma unroll
    for (int i = 0; i < 16; i++) xr[i] = __ldg(xp + i);

    float sq0 = 0.f, sq1 = 0.f, sk0 = 0.f, sk1 = 0.f;
    float* vpo = vp + node * 64;

#pragma unroll 1
    for (int jc = 0; jc < 16; jc++) {
        int j4 = jc * 4;
        u64 q01 = 0, q23 = 0, k01 = 0, k23 = 0, v01 = 0, v23 = 0;
#pragma unroll
        for (int kk4 = 0; kk4 < 16; kk4++) {
            float4 xv = xr[kk4];
#pragma unroll
            for (int c = 0; c < 4; c++) {
                float xs = (c == 0) ? xv.x : (c == 1) ? xv.y : (c == 2) ? xv.z : xv.w;
                int kk = kk4 * 4 + c;
                u64 xp2 = pack2(xs, xs);
                ulonglong2 wq2 = *reinterpret_cast<const ulonglong2*>(sW + kk * 64 + j4);
                ulonglong2 wk2 = *reinterpret_cast<const ulonglong2*>(sW + 4096 + kk * 64 + j4);
                ulonglong2 wv2 = *reinterpret_cast<const ulonglong2*>(sW + 8192 + kk * 64 + j4);
                ffma2(q01, xp2, wq2.x); ffma2(q23, xp2, wq2.y);
                ffma2(k01, xp2, wk2.x); ffma2(k23, xp2, wk2.y);
                ffma2(v01, xp2, wv2.x); ffma2(v23, xp2, wv2.y);
            }
        }
        float qv[4], kv[4], vv[4];
        unpack2(q01, qv[0], qv[1]); unpack2(q23, qv[2], qv[3]);
        unpack2(k01, kv[0], kv[1]); unpack2(k23, kv[2], kv[3]);
        unpack2(v01, vv[0], vv[1]); unpack2(v23, vv[2], vv[3]);

        float4 vout;
        float* vo = reinterpret_cast<float*>(&vout);
#pragma unroll
        for (int c = 0; c < 4; c++) {
            int j = j4 + c;
            int o = j & 31;
            float ej = __ldg(emb + j);
            float rj = __ldg(rel + j);
            float aq = __ldg(a_attn + o);
            float ak = __ldg(a_attn + 32 + o);
            float tq = tanh_h(qv[c] + ej);
            float tk = tanh_h(kv[c] + ej);
            if (jc < 8) { sq0 = fmaf(tq, aq, sq0); sk0 = fmaf(tk, ak, sk0); }
            else        { sq1 = fmaf(tq, aq, sq1); sk1 = fmaf(tk, ak, sk1); }
            vo[c] = vv[c] + rj;
        }
        *reinterpret_cast<float4*>(vpo + j4) = vout;
    }
    SQ[node * 2]     = sq0;
    SQ[node * 2 + 1] = sq1;
    SK[node * 2]     = sk0;
    SK[node * 2 + 1] = sk1;
}

// ---------------- edge pass: half-warp per edge, pipelined -----------------
__global__ void __launch_bounds__(256, 4) edge_kernel(
    const float* __restrict__ ea1,
    const int* __restrict__ row1, const int* __restrict__ col1,
    const float* __restrict__ SQ1, const float* __restrict__ SK1,
    const float* __restrict__ vp1,
    float* __restrict__ s1, float* __restrict__ agg1,
    const float* __restrict__ rel1,
    const float* __restrict__ ea2,
    const int* __restrict__ row2, const int* __restrict__ col2,
    const float* __restrict__ SQ2, const float* __restrict__ SK2,
    const float* __restrict__ vp2,
    float* __restrict__ s2, float* __restrict__ agg2,
    const float* __restrict__ rel2,
    const float* __restrict__ a_attn, const float* __restrict__ We)
{
    __shared__ ulonglong2 sWe[256];  // We: 16 rows x 16 float4 (64 ch)
    int tid = threadIdx.x;
    sWe[tid] = reinterpret_cast<const ulonglong2*>(We)[tid];
    __syncthreads();

    int r_sel = blockIdx.x & 1;
    const float* ea  = r_sel ? ea2  : ea1;
    const int*   row = r_sel ? row2 : row1;
    const int*   col = r_sel ? col2 : col1;
    const float* SQd = r_sel ? SQ2 : SQ1;
    const float* SKs = r_sel ? SK2 : SK1;
    const float* vps = r_sel ? vp2 : vp1;
    float*       s   = r_sel ? s2  : s1;
    float*       agg = r_sel ? agg2 : agg1;
    const float* relv = r_sel ? rel2 : rel1;

    int lane = tid & 31;
    int l = lane & 15;
    int sub = lane >> 4;
    int h = l >> 3;

    int gw = (((blockIdx.x >> 1) * blockDim.x) + tid) >> 5;
    int nw = ((gridDim.x >> 1) * blockDim.x) >> 5;

    float4 ae = __ldg(reinterpret_cast<const float4*>(a_attn + 96) + (l & 7));
    float4 r4 = __ldg(reinterpret_cast<const float4*>(relv) + l);
    float cc = tanh_h(r4.x) * ae.x + tanh_h(r4.y) * ae.y
             + tanh_h(r4.z) * ae.z + tanh_h(r4.w) * ae.w;
    cc += __shfl_xor_sync(0xffffffffu, cc, 4);
    cc += __shfl_xor_sync(0xffffffffu, cc, 2);
    cc += __shfl_xor_sync(0xffffffffu, cc, 1);

    // ---- prologue: load iteration 0 ----
    int ep = gw;
    bool act = ep < EHALF;
    int r = 0, c = 0;
    float4 A, B, C4, D;
    float sqv = 0.f, skv = 0.f;
    if (act) {
        int e = ep * 2 + sub;
        r = __ldg(row + e);
        c = __ldg(col + e);
        const float4* eap = reinterpret_cast<const float4*>(ea + (size_t)e * 16);
        A = __ldg(eap); B = __ldg(eap + 1); C4 = __ldg(eap + 2); D = __ldg(eap + 3);
        sqv = __ldg(SQd + 2 * c + h);
        skv = __ldg(SKs + 2 * r + h);
    }

    while (act) {
        // gather for current (r known since previous iteration / prologue)
        float4 v4 = __ldg(reinterpret_cast<const float4*>(vps + r * 64) + l);

        // ---- prefetch next iteration ----
        int epn = ep + nw;
        bool actn = epn < EHALF;
        int rn = 0, cn = 0;
        float4 An, Bn, Cn, Dn;
        if (actn) {
            int en = epn * 2 + sub;
            rn = __ldg(row + en);
            cn = __ldg(col + en);
            const float4* eapn = reinterpret_cast<const float4*>(ea + (size_t)en * 16);
            An = __ldg(eapn); Bn = __ldg(eapn + 1);
            Cn = __ldg(eapn + 2); Dn = __ldg(eapn + 3);
        }

        // ---- eb GEMM for current edge (f32x2) ----
        float eav[16] = {A.x, A.y, A.z, A.w, B.x, B.y, B.z, B.w,
                         C4.x, C4.y, C4.z, C4.w, D.x, D.y, D.z, D.w};
        u64 eb01 = 0, eb23 = 0;
#pragma unroll
        for (int k = 0; k < 16; k++) {
            u64 pk = pack2(eav[k], eav[k]);
            ulonglong2 w = sWe[k * 16 + l];
            ffma2(eb01, pk, w.x);
            ffma2(eb23, pk, w.y);
        }

        // dependent prefetches for next (rn, cn now available)
        float sqn = 0.f, skn = 0.f;
        if (actn) {
            sqn = __ldg(SQd + 2 * cn + h);
            skn = __ldg(SKs + 2 * rn + h);
        }

        // ---- score + message for current ----
        float ebx, eby, ebz, ebw;
        unpack2(eb01, ebx, eby);
        unpack2(eb23, ebz, ebw);

        float se = tanh_h(ebx) * ae.x + tanh_h(eby) * ae.y
                 + tanh_h(ebz) * ae.z + tanh_h(ebw) * ae.w;
        se += __shfl_xor_sync(0xffffffffu, se, 4);
        se += __shfl_xor_sync(0xffffffffu, se, 2);
        se += __shfl_xor_sync(0xffffffffu, se, 1);

        float score = se + cc + sqv + skv;
        float ex = __expf(score);

        float4 m;
        m.x = (v4.x + ebx) * ex;
        m.y = (v4.y + eby) * ex;
        m.z = (v4.z + ebz) * ex;
        m.w = (v4.w + ebw) * ex;

        red_add_v4(agg + c * 64 + 4 * l, m);
        if ((l & 7) == 0) atomicAdd(s + 2 * c + h, ex);

        // ---- rotate ----
        ep = epn; act = actn;
        r = rn; c = cn;
        A = An; B = Bn; C4 = Cn; D = Dn;
        sqv = sqn; skv = skn;
    }
}

// ---------------- epilogue: fin = (agg/s)@Wo + bo + x@Wr -------------------
// k-outer, j-inner with 32 accumulators (16 x f32x2). ~55 regs.
__global__ void __launch_bounds__(128) final_kernel(
    const float* __restrict__ agg_a, const float* __restrict__ s_a,
    const float* __restrict__ x_a,
    const float* __restrict__ Wo_a, const float* __restrict__ bo_a,
    const float* __restrict__ Wr_a,
    const float* __restrict__ agg_b, const float* __restrict__ s_b,
    const float* __restrict__ x_b,
    const float* __restrict__ Wo_b, const float* __restrict__ bo_b,
    const float* __restrict__ Wr_b,
    float* __restrict__ out, int pb)
{
    int typ = (blockIdx.x >= pb);
    int blk = typ ? (blockIdx.x - pb) : blockIdx.x;
    const float* agg = typ ? agg_b : agg_a;
    const float* s   = typ ? s_b   : s_a;
    const float* x   = typ ? x_b   : x_a;
    const float* Wo  = typ ? Wo_b  : Wo_a;
    const float* bo  = typ ? bo_b  : bo_a;
    const float* Wr  = typ ? Wr_b  : Wr_a;
    float* outp = out + (typ ? NN * 32 : 0);

    __shared__ float W2[128 * 32];   // rows 0..63 = Wo, 64..127 = Wr
    __shared__ float sbo[32];
    int tid = threadIdx.x;
    for (int i = tid; i < 2048; i += 128) {
        W2[i]        = Wo[i];
        W2[2048 + i] = Wr[i];
    }
    if (tid < 32) sbo[tid] = bo[tid];
    __syncthreads();

    int node = blk * 128 + tid;
    if (node >= NN) return;

    float s0 = __ldg(s + node * 2);
    float s1 = __ldg(s + node * 2 + 1);
    float i0 = (s0 != 0.f) ? __fdividef(1.f, s0) : 0.f;
    float i1 = (s1 != 0.f) ? __fdividef(1.f, s1) : 0.f;
    u64 inv0p = pack2(i0, i0);
    u64 inv1p = pack2(i1, i1);

    u64 acc[16];
#pragma unroll
    for (int p = 0; p < 16; p++) acc[p] = pack2(sbo[2 * p], sbo[2 * p + 1]);

    const float4* ap = reinterpret_cast<const float4*>(agg + node * 64);
    const float4* xp = reinterpret_cast<const float4*>(x + node * 64);

#pragma unroll 1
    for (int t = 0; t < 16; t++) {
        // 8 k-values per tile. tiles 0..7: agg (head 0 for t<4), tiles 8..15: x
        float4 b0, b1;
        if (t < 8) { b0 = __ldg(ap + 2 * t);       b1 = __ldg(ap + 2 * t + 1); }
        else       { b0 = __ldg(xp + 2 * (t - 8)); b1 = __ldg(xp + 2 * (t - 8) + 1); }
        float bv[8] = {b0.x, b0.y, b0.z, b0.w, b1.x, b1.y, b1.z, b1.w};
        bool is_agg = (t < 8);
        u64 invp = (t < 4) ? inv0p : inv1p;
#pragma unroll
        for (int kk = 0; kk < 8; kk++) {
            u64 cp = pack2(bv[kk], bv[kk]);
            if (is_agg) cp = mul2(cp, invp);
            const ulonglong2* wr = reinterpret_cast<const ulonglong2*>(W2 + (t * 8 + kk) * 32);
#pragma unroll
            for (int p2 = 0; p2 < 8; p2++) {
                ulonglong2 w = wr[p2];
                ffma2(acc[2 * p2], cp, w.x);
                ffma2(acc[2 * p2 + 1], cp, w.y);
            }
        }
    }

    float* op = outp + node * 32;
#pragma unroll
    for (int q = 0; q < 8; q++) {
        float4 o4;
        unpack2(acc[2 * q], o4.x, o4.y);
        unpack2(acc[2 * q + 1], o4.z, o4.w);
        *reinterpret_cast<float4*>(op + 4 * q) = o4;
    }
}

// ---------------- launch ---------------------------------------------------
extern "C" void kernel_launch(void* const* d_in, const int* in_sizes, int n_in,
                              void* d_out, int out_size) {
    const float* x_a   = (const float*)d_in[0];
    const float* x_b   = (const float*)d_in[1];
    const float* ea1   = (const float*)d_in[2];
    const float* ea2   = (const float*)d_in[3];
    const float* Wq_a  = (const float*)d_in[4];
    const float* Wk_a  = (const float*)d_in[5];
    const float* Wv_a  = (const float*)d_in[6];
    const float* Wq_b  = (const float*)d_in[7];
    const float* Wk_b  = (const float*)d_in[8];
    const float* Wv_b  = (const float*)d_in[9];
    const float* emb_a = (const float*)d_in[10];
    const float* emb_b = (const float*)d_in[11];
    const float* rel1  = (const float*)d_in[12];
    const float* rel2  = (const float*)d_in[13];
    const float* We    = (const float*)d_in[14];
    const float* a_at  = (const float*)d_in[15];
    const float* Wo_a  = (const float*)d_in[16];
    const float* bo_a  = (const float*)d_in[17];
    const float* Wo_b  = (const float*)d_in[18];
    const float* bo_b  = (const float*)d_in[19];
    const float* Wr_a  = (const float*)d_in[20];
    const float* Wr_b  = (const float*)d_in[21];
    const int*   row1  = (const int*)d_in[22];
    const int*   col1  = (const int*)d_in[23];
    const int*   row2  = (const int*)d_in[24];
    const int*   col2  = (const int*)d_in[25];
    float* out = (float*)d_out;

    void *pSQa, *pSKa, *pSQb, *pSKb, *pvpa, *pvpb, *psa, *psb, *pagga, *paggb;
    cudaGetSymbolAddress(&pSQa, g_SQa);
    cudaGetSymbolAddress(&pSKa, g_SKa);
    cudaGetSymbolAddress(&pSQb, g_SQb);
    cudaGetSymbolAddress(&pSKb, g_SKb);
    cudaGetSymbolAddress(&pvpa, g_vpa);
    cudaGetSymbolAddress(&pvpb, g_vpb);
    cudaGetSymbolAddress(&psa, g_sa);
    cudaGetSymbolAddress(&psb, g_sb);
    cudaGetSymbolAddress(&pagga, g_agga);
    cudaGetSymbolAddress(&paggb, g_aggb);

    // zero accumulators via memset nodes (graph-capturable)
    cudaMemsetAsync(pagga, 0, sizeof(float) * NN * 64);
    cudaMemsetAsync(paggb, 0, sizeof(float) * NN * 64);
    cudaMemsetAsync(psa, 0, sizeof(float) * NN * 2);
    cudaMemsetAsync(psb, 0, sizeof(float) * NN * 2);

    int pblocks = (NN + 127) / 128;
    proj_kernel<<<2 * pblocks, 128>>>(
        x_a, Wq_a, Wk_a, Wv_a, emb_a, rel1,
        (float*)pSQa, (float*)pSKa, (float*)pvpa,
        x_b, Wq_b, Wk_b, Wv_b, emb_b, rel2,
        (float*)pSQb, (float*)pSKb, (float*)pvpb,
        a_at, pblocks);

    edge_kernel<<<4096, 256>>>(
        ea1, row1, col1, (const float*)pSQb, (const float*)pSKa,
        (const float*)pvpa, (float*)psb, (float*)paggb, rel1,
        ea2, row2, col2, (const float*)pSQa, (const float*)pSKb,
        (const float*)pvpb, (float*)psa, (float*)pagga, rel2,
        a_at, We);

    final_kernel<<<2 * pblocks, 128>>>(
        (const float*)pagga, (const float*)psa, x_a, Wo_a, bo_a, Wr_a,
        (const float*)paggb, (const float*)psb, x_b, Wo_b, bo_b, Wr_b,
        out, pblocks);
}